// round 1
// baseline (speedup 1.0000x reference)
#include <cuda_runtime.h>
#include <math.h>

#define H 1024
#define E 48
#define R 32

// Scratch for precomputed partial products (no cudaMalloc allowed).
__device__ __align__(256) float g_P[E * H];  // ent @ W1[0:H]      (subject)
__device__ __align__(256) float g_Q[E * H];  // ent @ W1[2H:3H]    (object)
__device__ __align__(256) float g_B[R * H];  // rel @ W1[H:2H]     (relation)

// ---------------------------------------------------------------------------
// Kernel 1: P/Q/B precompute. grid = (64 colblocks, 3 sections), 256 threads.
// Thread (c = tid%16, rg = tid/16) computes rows {rg, rg+16, rg+32} x col.
// W1 is read from DRAM exactly once (each (section, colblock) panel is owned
// by one block). X rows are tiny (<=196KB) and served from L1/L2 broadcast.
// ---------------------------------------------------------------------------
template <int NM>
__device__ __forceinline__ void gemm_rows(
    const float* __restrict__ X, const float* __restrict__ W1,
    float* __restrict__ out, int woff, int col, int rg)
{
    const float4* x0 = reinterpret_cast<const float4*>(X + (rg +  0) * H);
    const float4* x1 = reinterpret_cast<const float4*>(X + (rg + 16) * H);
    const float4* x2 = reinterpret_cast<const float4*>(X + (rg + 32) * H);
    const float* wp = W1 + (size_t)woff * H + col;

    float a0 = 0.f, a1 = 0.f, a2 = 0.f;
#pragma unroll 2
    for (int k4 = 0; k4 < H / 4; k4++) {
        float4 v0 = x0[k4];
        float4 v1 = x1[k4];
        float4 v2 = (NM == 3) ? x2[k4] : make_float4(0.f, 0.f, 0.f, 0.f);
        int kb = k4 * 4;
        float w;
        w = wp[(size_t)(kb + 0) * H];
        a0 = fmaf(v0.x, w, a0); a1 = fmaf(v1.x, w, a1); if (NM == 3) a2 = fmaf(v2.x, w, a2);
        w = wp[(size_t)(kb + 1) * H];
        a0 = fmaf(v0.y, w, a0); a1 = fmaf(v1.y, w, a1); if (NM == 3) a2 = fmaf(v2.y, w, a2);
        w = wp[(size_t)(kb + 2) * H];
        a0 = fmaf(v0.z, w, a0); a1 = fmaf(v1.z, w, a1); if (NM == 3) a2 = fmaf(v2.z, w, a2);
        w = wp[(size_t)(kb + 3) * H];
        a0 = fmaf(v0.w, w, a0); a1 = fmaf(v1.w, w, a1); if (NM == 3) a2 = fmaf(v2.w, w, a2);
    }
    out[(rg +  0) * H + col] = a0;
    out[(rg + 16) * H + col] = a1;
    if (NM == 3) out[(rg + 32) * H + col] = a2;
}

__global__ void __launch_bounds__(256)
precompute_kernel(const float* __restrict__ ent,
                  const float* __restrict__ rel,
                  const float* __restrict__ W1)
{
    int sec = blockIdx.y;
    int col = blockIdx.x * 16 + (threadIdx.x & 15);
    int rg  = threadIdx.x >> 4;  // 0..15

    if (sec == 0) {
        gemm_rows<3>(ent, W1, g_P, 0,     col, rg);
    } else if (sec == 1) {
        gemm_rows<3>(ent, W1, g_Q, 2 * H, col, rg);
    } else {
        gemm_rows<2>(rel, W1, g_B, H,     col, rg);
    }
}

// ---------------------------------------------------------------------------
// Kernel 2: scores. grid = (48, 48) -> (j, i). 256 threads = 8 warps.
// Masked (i,j) pairs: write 32 zeros, exit. Active pairs: each warp holds
// D[h] = P[i,h]+Q[j,h]+b1[h] and W2[h] for its 32 h-values per lane in
// registers, loops 4 relations, reads B rows via LDG.128 (L1-resident),
// shfl-reduces, applies sigmoid.
// ---------------------------------------------------------------------------
__global__ void __launch_bounds__(256)
score_kernel(const float* __restrict__ b1v,
             const float* __restrict__ W2,
             const float* __restrict__ b2v,
             const int*   __restrict__ starts,
             const int*   __restrict__ maxd_p,
             float*       __restrict__ out)
{
    int j = blockIdx.x;
    int i = blockIdx.y;
    float* outp = out + ((size_t)i * E + j) * R;

    int si = starts[i];
    int sj = starts[j];
    int maxd = maxd_p[0];
    int dist = si - sj; if (dist < 0) dist = -dist;
    bool active = (i != j) && (dist <= maxd);

    if (!active) {
        if (threadIdx.x < R) outp[threadIdx.x] = 0.f;
        return;
    }

    int lane = threadIdx.x & 31;
    int w    = threadIdx.x >> 5;  // 0..7

    const float4* P4  = reinterpret_cast<const float4*>(g_P + (size_t)i * H);
    const float4* Q4  = reinterpret_cast<const float4*>(g_Q + (size_t)j * H);
    const float4* B14 = reinterpret_cast<const float4*>(b1v);
    const float4* W24 = reinterpret_cast<const float4*>(W2);

    float d[8][4];
    float w2r[8][4];
#pragma unroll
    for (int q = 0; q < 8; q++) {
        int idx = lane + q * 32;          // float4 index; h = 4*idx
        float4 p  = P4[idx];
        float4 qq = Q4[idx];
        float4 bb = B14[idx];
        float4 ww = W24[idx];
        d[q][0] = p.x + qq.x + bb.x;
        d[q][1] = p.y + qq.y + bb.y;
        d[q][2] = p.z + qq.z + bb.z;
        d[q][3] = p.w + qq.w + bb.w;
        w2r[q][0] = ww.x; w2r[q][1] = ww.y; w2r[q][2] = ww.z; w2r[q][3] = ww.w;
    }

    float acc[4];
    const float4* B4 = reinterpret_cast<const float4*>(g_B);
#pragma unroll
    for (int kk = 0; kk < 4; kk++) {
        int k = w * 4 + kk;
        const float4* Brow = B4 + (size_t)k * (H / 4);
        float a = 0.f;
#pragma unroll
        for (int q = 0; q < 8; q++) {
            float4 bv = Brow[lane + q * 32];
            float t;
            t = fmaxf(d[q][0] + bv.x, 0.f); a = fmaf(t, w2r[q][0], a);
            t = fmaxf(d[q][1] + bv.y, 0.f); a = fmaf(t, w2r[q][1], a);
            t = fmaxf(d[q][2] + bv.z, 0.f); a = fmaf(t, w2r[q][2], a);
            t = fmaxf(d[q][3] + bv.w, 0.f); a = fmaf(t, w2r[q][3], a);
        }
        acc[kk] = a;
    }

    // Warp tree reductions (4 independent chains interleave for ILP).
#pragma unroll
    for (int kk = 0; kk < 4; kk++) {
        float a = acc[kk];
#pragma unroll
        for (int off = 16; off > 0; off >>= 1)
            a += __shfl_xor_sync(0xffffffffu, a, off);
        acc[kk] = a;
    }

    if (lane == 0) {
        float b2 = b2v[0];
#pragma unroll
        for (int kk = 0; kk < 4; kk++) {
            float x = acc[kk] + b2;
            float s = 1.0f / (1.0f + __expf(-x));
            outp[w * 4 + kk] = s;
        }
    }
}

// ---------------------------------------------------------------------------
// Inputs (metadata order):
//  0 entity_emb   f32 [48,1024]
//  1 rel_emb      f32 [32,1024]
//  2 W1           f32 [3072,1024]
//  3 b1           f32 [1024]
//  4 W2           f32 [1024,1]
//  5 b2           f32 [1]
//  6 entity_starts i32 [48]
//  7 max_distance i32 scalar
// Output: f32 [48,48,32]
// ---------------------------------------------------------------------------
extern "C" void kernel_launch(void* const* d_in, const int* in_sizes, int n_in,
                              void* d_out, int out_size)
{
    const float* ent    = (const float*)d_in[0];
    const float* rel    = (const float*)d_in[1];
    const float* W1     = (const float*)d_in[2];
    const float* b1     = (const float*)d_in[3];
    const float* W2     = (const float*)d_in[4];
    const float* b2     = (const float*)d_in[5];
    const int*   starts = (const int*)  d_in[6];
    const int*   maxd   = (const int*)  d_in[7];
    float* out = (float*)d_out;

    precompute_kernel<<<dim3(H / 16, 3), 256>>>(ent, rel, W1);
    score_kernel<<<dim3(E, E), 256>>>(b1, W2, b2, starts, maxd, out);
}

// round 2
// speedup vs baseline: 1.5659x; 1.5659x over previous
#include <cuda_runtime.h>
#include <math.h>

#define H 1024
#define E 48
#define R 32
#define KC 16          // k-chunks in precompute
#define KCHUNK 64      // H / KC
#define TOTROWS 128    // 48 P + 48 Q + 32 B rows

typedef unsigned long long ull;

// Combined precompute result: [0:48H) = P+b1 rows, [48H:96H) = Q rows, [96H:128H) = B rows
__device__ __align__(16) float g_PQB[TOTROWS * H];
// Per-k-chunk partials (8 MB)
__device__ __align__(16) float g_part[KC * TOTROWS * H];

// ---- packed f32x2 helpers (Blackwell) ------------------------------------
__device__ __forceinline__ ull f2fma(ull a, ull b, ull c) {
    ull d;
    asm("fma.rn.f32x2 %0, %1, %2, %3;" : "=l"(d) : "l"(a), "l"(b), "l"(c));
    return d;
}
__device__ __forceinline__ ull f2add(ull a, ull b) {
    ull d;
    asm("add.rn.f32x2 %0, %1, %2;" : "=l"(d) : "l"(a), "l"(b));
    return d;
}
__device__ __forceinline__ ull f2pack(float lo, float hi) {
    ull d;
    asm("mov.b64 %0, {%1, %2};" : "=l"(d) : "f"(lo), "f"(hi));
    return d;
}
__device__ __forceinline__ void f2unpack(ull v, float& lo, float& hi) {
    asm("mov.b64 {%0, %1}, %2;" : "=f"(lo), "=f"(hi) : "l"(v));
}

// ---------------------------------------------------------------------------
// Kernel 1: partial GEMMs.  grid = (64, 5): x = nb(4) * kc(16); y = row-group.
// Block = 128 threads, each thread owns 2 output columns (f32x2), M rows in
// registers. X chunk is staged in smem pre-duplicated as {x,x} pairs.
// ---------------------------------------------------------------------------
template <int M>
__device__ __forceinline__ void gemm_chunk(
    const float* __restrict__ X, const float* __restrict__ W1,
    int mbase, int woff, int secbase, int kc, int n, int tid)
{
    __shared__ __align__(16) ull xs[32][KCHUNK];

    const int k0 = kc * KCHUNK;

    // cooperative X stage: M*KCHUNK floats, duplicated into packed pairs
    for (int idx = tid; idx < M * KCHUNK; idx += 128) {
        int m = idx >> 6;          // KCHUNK = 64
        int kk = idx & 63;
        float v = X[(size_t)(mbase + m) * H + k0 + kk];
        xs[m][kk] = f2pack(v, v);
    }
    __syncthreads();

    ull acc[M];
#pragma unroll
    for (int m = 0; m < M; m++) acc[m] = 0ull;

    const float* wbase = W1 + (size_t)(woff + k0) * H + n;

    for (int kkb = 0; kkb < KCHUNK; kkb += 8) {
        ull w[8];
#pragma unroll
        for (int r = 0; r < 8; r++)
            w[r] = *(const ull*)(wbase + (size_t)(kkb + r) * H);
#pragma unroll
        for (int m = 0; m < M; m++) {
#pragma unroll
            for (int p = 0; p < 4; p++) {
                ulonglong2 x2 = *(const ulonglong2*)&xs[m][kkb + 2 * p];
                acc[m] = f2fma(x2.x, w[2 * p + 0], acc[m]);
                acc[m] = f2fma(x2.y, w[2 * p + 1], acc[m]);
            }
        }
    }

    float* dst = g_part + (size_t)kc * (TOTROWS * H) + secbase + n;
#pragma unroll
    for (int m = 0; m < M; m++)
        *(ull*)(dst + (size_t)(mbase + m) * H) = acc[m];
}

__global__ void __launch_bounds__(128)
precompute_kernel(const float* __restrict__ ent,
                  const float* __restrict__ rel,
                  const float* __restrict__ W1)
{
    int g   = blockIdx.y;          // 0..4
    int kc  = blockIdx.x & 15;
    int nb  = blockIdx.x >> 4;     // 0..3
    int tid = threadIdx.x;
    int n   = nb * 256 + tid * 2;

    if (g == 0)      gemm_chunk<24>(ent, W1,  0, 0,       0,      kc, n, tid);
    else if (g == 1) gemm_chunk<24>(ent, W1, 24, 0,       0,      kc, n, tid);
    else if (g == 2) gemm_chunk<24>(ent, W1,  0, 2 * H,   48 * H, kc, n, tid);
    else if (g == 3) gemm_chunk<24>(ent, W1, 24, 2 * H,   48 * H, kc, n, tid);
    else             gemm_chunk<32>(rel, W1,  0, 1 * H,   96 * H, kc, n, tid);
}

// ---------------------------------------------------------------------------
// Kernel 2: reduce partials; fold b1 into the P section.
// 32768 float4 outputs, 128 blocks x 256 threads.
// ---------------------------------------------------------------------------
__global__ void __launch_bounds__(256)
reduce_kernel(const float* __restrict__ b1v)
{
    int idx4 = blockIdx.x * 256 + threadIdx.x;   // < 32768
    const float4* part4 = (const float4*)g_part;
    float4 s = part4[idx4];
#pragma unroll
    for (int c = 1; c < KC; c++) {
        float4 p = part4[(size_t)c * 32768 + idx4];
        s.x += p.x; s.y += p.y; s.z += p.z; s.w += p.w;
    }
    if (idx4 < 48 * 256) {   // P section: fold b1
        float4 bb = ((const float4*)b1v)[idx4 & 255];
        s.x += bb.x; s.y += bb.y; s.z += bb.z; s.w += bb.w;
    }
    ((float4*)g_PQB)[idx4] = s;
}

// ---------------------------------------------------------------------------
// Kernel 3: scores. grid = (24, 48): block = (i, pair of j). 256 thr = 8 warps,
// warp w owns relations 4w..4w+3. P'[i] and W2 slices live in registers across
// both j. Inner math is packed f32x2 except the relu (scalar FMNMX on halves).
// ---------------------------------------------------------------------------
__global__ void __launch_bounds__(256)
score_kernel(const float* __restrict__ W2,
             const float* __restrict__ b2v,
             const int*   __restrict__ starts,
             const int*   __restrict__ maxd_p,
             float*       __restrict__ out)
{
    int i    = blockIdx.y;
    int j0   = blockIdx.x * 2;
    int lane = threadIdx.x & 31;
    int w    = threadIdx.x >> 5;

    int si   = starts[i];
    int maxd = maxd_p[0];
    float b2 = b2v[0];

    const ulonglong2* P2  = (const ulonglong2*)(g_PQB + (size_t)i * H);
    const ulonglong2* W24 = (const ulonglong2*)W2;

    ull pd01[8], pd23[8], w01[8], w23[8];
#pragma unroll
    for (int q = 0; q < 8; q++) {
        ulonglong2 p  = P2 [lane + 32 * q];
        ulonglong2 ww = W24[lane + 32 * q];
        pd01[q] = p.x;  pd23[q] = p.y;
        w01[q]  = ww.x; w23[q]  = ww.y;
    }

#pragma unroll
    for (int jj = 0; jj < 2; jj++) {
        int j = j0 + jj;
        int sj = starts[j];
        int dist = si - sj; if (dist < 0) dist = -dist;
        bool active = (i != j) && (dist <= maxd);
        float* outp = out + ((size_t)i * E + j) * R;

        if (!active) {
            if (threadIdx.x < R) outp[threadIdx.x] = 0.f;
            continue;
        }

        const ulonglong2* Q2 = (const ulonglong2*)(g_PQB + (size_t)(E + j) * H);
        ull d01[8], d23[8];
#pragma unroll
        for (int q = 0; q < 8; q++) {
            ulonglong2 qq = Q2[lane + 32 * q];
            d01[q] = f2add(pd01[q], qq.x);
            d23[q] = f2add(pd23[q], qq.y);
        }

#pragma unroll
        for (int kk = 0; kk < 4; kk++) {
            int k = w * 4 + kk;
            const ulonglong2* B2 = (const ulonglong2*)(g_PQB + (size_t)(2 * E + k) * H);
            ull a01 = 0ull, a23 = 0ull;
#pragma unroll
            for (int q = 0; q < 8; q++) {
                ulonglong2 bv = B2[lane + 32 * q];
                ull s01 = f2add(d01[q], bv.x);
                ull s23 = f2add(d23[q], bv.y);
                float t0, t1, t2, t3;
                f2unpack(s01, t0, t1);
                f2unpack(s23, t2, t3);
                t0 = fmaxf(t0, 0.f); t1 = fmaxf(t1, 0.f);
                t2 = fmaxf(t2, 0.f); t3 = fmaxf(t3, 0.f);
                a01 = f2fma(f2pack(t0, t1), w01[q], a01);
                a23 = f2fma(f2pack(t2, t3), w23[q], a23);
            }
            float r0, r1, r2, r3;
            f2unpack(a01, r0, r1);
            f2unpack(a23, r2, r3);
            float a = (r0 + r1) + (r2 + r3);
#pragma unroll
            for (int off = 16; off > 0; off >>= 1)
                a += __shfl_xor_sync(0xffffffffu, a, off);
            if (lane == 0) {
                float x = a + b2;
                outp[k] = 1.0f / (1.0f + __expf(-x));
            }
        }
    }
}

// ---------------------------------------------------------------------------
// Inputs (metadata order):
//  0 entity_emb f32[48,1024]  1 rel_emb f32[32,1024]  2 W1 f32[3072,1024]
//  3 b1 f32[1024]  4 W2 f32[1024,1]  5 b2 f32[1]
//  6 entity_starts i32[48]    7 max_distance i32
// Output: f32 [48,48,32]
// ---------------------------------------------------------------------------
extern "C" void kernel_launch(void* const* d_in, const int* in_sizes, int n_in,
                              void* d_out, int out_size)
{
    const float* ent    = (const float*)d_in[0];
    const float* rel    = (const float*)d_in[1];
    const float* W1     = (const float*)d_in[2];
    const float* b1     = (const float*)d_in[3];
    const float* W2     = (const float*)d_in[4];
    const float* b2     = (const float*)d_in[5];
    const int*   starts = (const int*)  d_in[6];
    const int*   maxd   = (const int*)  d_in[7];
    float* out = (float*)d_out;

    precompute_kernel<<<dim3(64, 5), 128>>>(ent, rel, W1);
    reduce_kernel<<<128, 256>>>(b1);
    score_kernel<<<dim3(24, 48), 256>>>(W2, b2, starts, maxd, out);
}

// round 3
// speedup vs baseline: 1.8801x; 1.2007x over previous
#include <cuda_runtime.h>
#include <math.h>

#define H 1024
#define E 48
#define R 32
#define KC 16          // k-chunks in precompute
#define KCHUNK 64      // H / KC
#define TOTROWS 128    // 48 P + 48 Q + 32 B rows
#define MROWS 8        // rows per precompute block

typedef unsigned long long ull;

// Combined precompute result: [0:48H) = P+b1 rows, [48H:96H) = Q rows, [96H:128H) = B rows
__device__ __align__(16) float g_PQB[TOTROWS * H];
// Per-k-chunk partials (8 MB)
__device__ __align__(16) float g_part[KC * TOTROWS * H];

// ---- packed f32x2 helpers (Blackwell) ------------------------------------
__device__ __forceinline__ ull f2fma(ull a, ull b, ull c) {
    ull d;
    asm("fma.rn.f32x2 %0, %1, %2, %3;" : "=l"(d) : "l"(a), "l"(b), "l"(c));
    return d;
}
__device__ __forceinline__ ull f2add(ull a, ull b) {
    ull d;
    asm("add.rn.f32x2 %0, %1, %2;" : "=l"(d) : "l"(a), "l"(b));
    return d;
}
__device__ __forceinline__ ull f2pack(float lo, float hi) {
    ull d;
    asm("mov.b64 %0, {%1, %2};" : "=l"(d) : "f"(lo), "f"(hi));
    return d;
}
__device__ __forceinline__ void f2unpack(ull v, float& lo, float& hi) {
    asm("mov.b64 {%0, %1}, %2;" : "=f"(lo), "=f"(hi) : "l"(v));
}

// ---------------------------------------------------------------------------
// Kernel 1: partial GEMMs, occupancy-first tiling.
// grid = (64, 16): x = kc(16) + 16*nb(4 column panels of 256);
//                  y = row-group (16 groups of 8 rows).
// Block = 128 threads; thread owns 2 output columns (one f32x2), 8 rows.
// X chunk (8 rows x 64 k) staged in smem pre-duplicated as {x,x} pairs;
// inner loop: 8 LDG.64 (W1, coalesced, read once) + 32 LDS.128 (broadcast)
// + 64 packed FMAs per 8-k batch.
// ---------------------------------------------------------------------------
__global__ void __launch_bounds__(128)
precompute_kernel(const float* __restrict__ ent,
                  const float* __restrict__ rel,
                  const float* __restrict__ W1)
{
    __shared__ __align__(16) ull xs[MROWS][KCHUNK];

    int g   = blockIdx.y;          // 0..15 row group
    int kc  = blockIdx.x & 15;
    int nb  = blockIdx.x >> 4;     // 0..3
    int tid = threadIdx.x;
    int n   = nb * 256 + tid * 2;

    const float* X;
    int xrow, woff, secrow;
    if (g < 6)       { X = ent; xrow = g * 8;        woff = 0;     secrow = g * 8; }
    else if (g < 12) { X = ent; xrow = (g - 6) * 8;  woff = 2 * H; secrow = 48 + (g - 6) * 8; }
    else             { X = rel; xrow = (g - 12) * 8; woff = H;     secrow = 96 + (g - 12) * 8; }

    const int k0 = kc * KCHUNK;

    // stage X chunk: 8*64 = 512 packed entries, 4 per thread
#pragma unroll
    for (int t = 0; t < 4; t++) {
        int idx = tid + t * 128;
        int m  = idx >> 6;
        int kk = idx & 63;
        float v = X[(size_t)(xrow + m) * H + k0 + kk];
        xs[m][kk] = f2pack(v, v);
    }
    __syncthreads();

    ull acc[MROWS];
#pragma unroll
    for (int m = 0; m < MROWS; m++) acc[m] = 0ull;

    const float* wbase = W1 + (size_t)(woff + k0) * H + n;

    for (int kk = 0; kk < KCHUNK; kk += 8) {
        ull w[8];
#pragma unroll
        for (int r = 0; r < 8; r++)
            w[r] = *(const ull*)(wbase + (size_t)(kk + r) * H);
#pragma unroll
        for (int m = 0; m < MROWS; m++) {
#pragma unroll
            for (int p = 0; p < 4; p++) {
                ulonglong2 x2 = *(const ulonglong2*)&xs[m][kk + 2 * p];
                acc[m] = f2fma(x2.x, w[2 * p + 0], acc[m]);
                acc[m] = f2fma(x2.y, w[2 * p + 1], acc[m]);
            }
        }
    }

    float* dst = g_part + (size_t)kc * (TOTROWS * H) + (size_t)secrow * H + n;
#pragma unroll
    for (int m = 0; m < MROWS; m++)
        *(ull*)(dst + (size_t)m * H) = acc[m];
}

// ---------------------------------------------------------------------------
// Kernel 2: reduce partials; fold b1 into the P section.
// 32768 float4 outputs, 128 blocks x 256 threads. Partials are L2-hot.
// ---------------------------------------------------------------------------
__global__ void __launch_bounds__(256)
reduce_kernel(const float* __restrict__ b1v)
{
    int idx4 = blockIdx.x * 256 + threadIdx.x;   // < 32768
    const float4* part4 = (const float4*)g_part;
    float4 s = part4[idx4];
#pragma unroll
    for (int c = 1; c < KC; c++) {
        float4 p = part4[(size_t)c * 32768 + idx4];
        s.x += p.x; s.y += p.y; s.z += p.z; s.w += p.w;
    }
    if (idx4 < 48 * 256) {   // P section: fold b1
        float4 bb = ((const float4*)b1v)[idx4 & 255];
        s.x += bb.x; s.y += bb.y; s.z += bb.z; s.w += bb.w;
    }
    ((float4*)g_PQB)[idx4] = s;
}

// ---------------------------------------------------------------------------
// Kernel 3: scores. grid = (24, 48): block = (pair of j, i). 256 thr = 8 warps,
// warp w owns relations 4w..4w+3. P'[i] and W2 slices live in registers across
// both j. Inner math is packed f32x2 except the relu (scalar FMNMX on halves).
// ---------------------------------------------------------------------------
__global__ void __launch_bounds__(256)
score_kernel(const float* __restrict__ W2,
             const float* __restrict__ b2v,
             const int*   __restrict__ starts,
             const int*   __restrict__ maxd_p,
             float*       __restrict__ out)
{
    int i    = blockIdx.y;
    int j0   = blockIdx.x * 2;
    int lane = threadIdx.x & 31;
    int w    = threadIdx.x >> 5;

    int si   = starts[i];
    int maxd = maxd_p[0];
    float b2 = b2v[0];

    const ulonglong2* P2  = (const ulonglong2*)(g_PQB + (size_t)i * H);
    const ulonglong2* W24 = (const ulonglong2*)W2;

    ull pd01[8], pd23[8], w01[8], w23[8];
#pragma unroll
    for (int q = 0; q < 8; q++) {
        ulonglong2 p  = P2 [lane + 32 * q];
        ulonglong2 ww = W24[lane + 32 * q];
        pd01[q] = p.x;  pd23[q] = p.y;
        w01[q]  = ww.x; w23[q]  = ww.y;
    }

#pragma unroll
    for (int jj = 0; jj < 2; jj++) {
        int j = j0 + jj;
        int sj = starts[j];
        int dist = si - sj; if (dist < 0) dist = -dist;
        bool active = (i != j) && (dist <= maxd);
        float* outp = out + ((size_t)i * E + j) * R;

        if (!active) {
            if (threadIdx.x < R) outp[threadIdx.x] = 0.f;
            continue;
        }

        const ulonglong2* Q2 = (const ulonglong2*)(g_PQB + (size_t)(E + j) * H);
        ull d01[8], d23[8];
#pragma unroll
        for (int q = 0; q < 8; q++) {
            ulonglong2 qq = Q2[lane + 32 * q];
            d01[q] = f2add(pd01[q], qq.x);
            d23[q] = f2add(pd23[q], qq.y);
        }

#pragma unroll
        for (int kk = 0; kk < 4; kk++) {
            int k = w * 4 + kk;
            const ulonglong2* B2 = (const ulonglong2*)(g_PQB + (size_t)(2 * E + k) * H);
            ull a01 = 0ull, a23 = 0ull;
#pragma unroll
            for (int q = 0; q < 8; q++) {
                ulonglong2 bv = B2[lane + 32 * q];
                ull s01 = f2add(d01[q], bv.x);
                ull s23 = f2add(d23[q], bv.y);
                float t0, t1, t2, t3;
                f2unpack(s01, t0, t1);
                f2unpack(s23, t2, t3);
                t0 = fmaxf(t0, 0.f); t1 = fmaxf(t1, 0.f);
                t2 = fmaxf(t2, 0.f); t3 = fmaxf(t3, 0.f);
                a01 = f2fma(f2pack(t0, t1), w01[q], a01);
                a23 = f2fma(f2pack(t2, t3), w23[q], a23);
            }
            float r0, r1, r2, r3;
            f2unpack(a01, r0, r1);
            f2unpack(a23, r2, r3);
            float a = (r0 + r1) + (r2 + r3);
#pragma unroll
            for (int off = 16; off > 0; off >>= 1)
                a += __shfl_xor_sync(0xffffffffu, a, off);
            if (lane == 0) {
                float x = a + b2;
                outp[k] = 1.0f / (1.0f + __expf(-x));
            }
        }
    }
}

// ---------------------------------------------------------------------------
// Inputs (metadata order):
//  0 entity_emb f32[48,1024]  1 rel_emb f32[32,1024]  2 W1 f32[3072,1024]
//  3 b1 f32[1024]  4 W2 f32[1024,1]  5 b2 f32[1]
//  6 entity_starts i32[48]    7 max_distance i32
// Output: f32 [48,48,32]
// ---------------------------------------------------------------------------
extern "C" void kernel_launch(void* const* d_in, const int* in_sizes, int n_in,
                              void* d_out, int out_size)
{
    const float* ent    = (const float*)d_in[0];
    const float* rel    = (const float*)d_in[1];
    const float* W1     = (const float*)d_in[2];
    const float* b1     = (const float*)d_in[3];
    const float* W2     = (const float*)d_in[4];
    const float* b2     = (const float*)d_in[5];
    const int*   starts = (const int*)  d_in[6];
    const int*   maxd   = (const int*)  d_in[7];
    float* out = (float*)d_out;

    precompute_kernel<<<dim3(64, 16), 128>>>(ent, rel, W1);
    reduce_kernel<<<128, 256>>>(b1);
    score_kernel<<<dim3(24, 48), 256>>>(W2, b2, starts, maxd, out);
}

// round 4
// speedup vs baseline: 1.9991x; 1.0633x over previous
#include <cuda_runtime.h>
#include <math.h>

#define H 1024
#define E 48
#define R 32
#define KC 16          // k-chunks in precompute
#define KCHUNK 64      // H / KC
#define TOTROWS 128    // 48 P + 48 Q + 32 B rows
#define MROWS 8        // rows per precompute block

typedef unsigned long long ull;

// Combined precompute result: [0:48H) = P+b1 rows, [48H:96H) = Q rows, [96H:128H) = B rows
__device__ __align__(16) float g_PQB[TOTROWS * H];
// Per-k-chunk partials (8 MB)
__device__ __align__(16) float g_part[KC * TOTROWS * H];

// ---- packed f32x2 helpers (Blackwell) ------------------------------------
__device__ __forceinline__ ull f2fma(ull a, ull b, ull c) {
    ull d;
    asm("fma.rn.f32x2 %0, %1, %2, %3;" : "=l"(d) : "l"(a), "l"(b), "l"(c));
    return d;
}
__device__ __forceinline__ ull f2add(ull a, ull b) {
    ull d;
    asm("add.rn.f32x2 %0, %1, %2;" : "=l"(d) : "l"(a), "l"(b));
    return d;
}
__device__ __forceinline__ ull f2pack(float lo, float hi) {
    ull d;
    asm("mov.b64 %0, {%1, %2};" : "=l"(d) : "f"(lo), "f"(hi));
    return d;
}
__device__ __forceinline__ void f2unpack(ull v, float& lo, float& hi) {
    asm("mov.b64 {%0, %1}, %2;" : "=f"(lo), "=f"(hi) : "l"(v));
}

// ---------------------------------------------------------------------------
// Kernel 1: partial GEMMs, double-buffered W prefetch.
// grid = (64, 16): x = kc(16) + 16*nb(4 column panels of 256);
//                  y = row-group (16 groups of 8 rows).
// Block = 128 threads; thread owns 2 output columns (one f32x2), 8 rows.
// Fully-unrolled 8-k batches; batch b+1's W loads are issued before batch b's
// FMAs consume their registers, so DRAM latency is exposed once per block.
// ---------------------------------------------------------------------------
__global__ void __launch_bounds__(128, 8)
precompute_kernel(const float* __restrict__ ent,
                  const float* __restrict__ rel,
                  const float* __restrict__ W1)
{
    __shared__ __align__(16) ull xs[MROWS][KCHUNK];

    int g   = blockIdx.y;          // 0..15 row group
    int kc  = blockIdx.x & 15;
    int nb  = blockIdx.x >> 4;     // 0..3
    int tid = threadIdx.x;
    int n   = nb * 256 + tid * 2;

    const float* X;
    int xrow, woff, secrow;
    if (g < 6)       { X = ent; xrow = g * 8;        woff = 0;     secrow = g * 8; }
    else if (g < 12) { X = ent; xrow = (g - 6) * 8;  woff = 2 * H; secrow = 48 + (g - 6) * 8; }
    else             { X = rel; xrow = (g - 12) * 8; woff = H;     secrow = 96 + (g - 12) * 8; }

    const int k0 = kc * KCHUNK;
    const float* wbase = W1 + (size_t)(woff + k0) * H + n;

    // issue first W batch before staging X (overlap DRAM latency with LDS work)
    ull wc[8];
#pragma unroll
    for (int r = 0; r < 8; r++)
        wc[r] = *(const ull*)(wbase + (size_t)r * H);

    // stage X chunk: 8*64 = 512 packed entries, 4 per thread
#pragma unroll
    for (int t = 0; t < 4; t++) {
        int idx = tid + t * 128;
        int m  = idx >> 6;
        int kk = idx & 63;
        float v = X[(size_t)(xrow + m) * H + k0 + kk];
        xs[m][kk] = f2pack(v, v);
    }
    __syncthreads();

    ull acc[MROWS];
#pragma unroll
    for (int m = 0; m < MROWS; m++) acc[m] = 0ull;

#pragma unroll
    for (int b = 0; b < KCHUNK / 8; b++) {
        ull wn[8];
        if (b < KCHUNK / 8 - 1) {
#pragma unroll
            for (int r = 0; r < 8; r++)
                wn[r] = *(const ull*)(wbase + (size_t)((b + 1) * 8 + r) * H);
        }
        int kk = b * 8;
#pragma unroll
        for (int m = 0; m < MROWS; m++) {
#pragma unroll
            for (int p = 0; p < 4; p++) {
                ulonglong2 x2 = *(const ulonglong2*)&xs[m][kk + 2 * p];
                acc[m] = f2fma(x2.x, wc[2 * p + 0], acc[m]);
                acc[m] = f2fma(x2.y, wc[2 * p + 1], acc[m]);
            }
        }
#pragma unroll
        for (int r = 0; r < 8; r++) wc[r] = wn[r];
    }

    float* dst = g_part + (size_t)kc * (TOTROWS * H) + (size_t)secrow * H + n;
#pragma unroll
    for (int m = 0; m < MROWS; m++)
        *(ull*)(dst + (size_t)m * H) = acc[m];
}

// ---------------------------------------------------------------------------
// Kernel 2: reduce partials; fold b1 into the P section. L2-hot.
// ---------------------------------------------------------------------------
__global__ void __launch_bounds__(256)
reduce_kernel(const float* __restrict__ b1v)
{
    int idx4 = blockIdx.x * 256 + threadIdx.x;   // < 32768
    const float4* part4 = (const float4*)g_part;
    float4 s = part4[idx4];
#pragma unroll
    for (int c = 1; c < KC; c++) {
        float4 p = part4[(size_t)c * 32768 + idx4];
        s.x += p.x; s.y += p.y; s.z += p.z; s.w += p.w;
    }
    if (idx4 < 48 * 256) {   // P section: fold b1
        float4 bb = ((const float4*)b1v)[idx4 & 255];
        s.x += bb.x; s.y += bb.y; s.z += bb.z; s.w += bb.w;
    }
    ((float4*)g_PQB)[idx4] = s;
}

// ---------------------------------------------------------------------------
// Kernel 3: scores. grid = (24, 48): block = (pair of j, i). 256 thr = 8 warps,
// warp w owns relations 4w..4w+3. B loads are shared across the j-pair when
// both are active (halves L1 traffic); single-pair path otherwise.
// ---------------------------------------------------------------------------
template <int NP>
__device__ __forceinline__ void score_pairs(
    const ull d01[][8], const ull d23[][8],
    const ull* __restrict__ w01, const ull* __restrict__ w23,
    int lane, int w, float b2, float* outp0, float* outp1)
{
#pragma unroll
    for (int kk = 0; kk < 4; kk++) {
        int k = w * 4 + kk;
        const ulonglong2* B2 = (const ulonglong2*)(g_PQB + (size_t)(2 * E + k) * H);
        ull a01[NP], a23[NP];
#pragma unroll
        for (int p = 0; p < NP; p++) { a01[p] = 0ull; a23[p] = 0ull; }
#pragma unroll
        for (int q = 0; q < 8; q++) {
            ulonglong2 bv = B2[lane + 32 * q];
#pragma unroll
            for (int p = 0; p < NP; p++) {
                ull s01 = f2add(d01[p][q], bv.x);
                ull s23 = f2add(d23[p][q], bv.y);
                float t0, t1, t2, t3;
                f2unpack(s01, t0, t1);
                f2unpack(s23, t2, t3);
                t0 = fmaxf(t0, 0.f); t1 = fmaxf(t1, 0.f);
                t2 = fmaxf(t2, 0.f); t3 = fmaxf(t3, 0.f);
                a01[p] = f2fma(f2pack(t0, t1), w01[q], a01[p]);
                a23[p] = f2fma(f2pack(t2, t3), w23[q], a23[p]);
            }
        }
#pragma unroll
        for (int p = 0; p < NP; p++) {
            float r0, r1, r2, r3;
            f2unpack(a01[p], r0, r1);
            f2unpack(a23[p], r2, r3);
            float a = (r0 + r1) + (r2 + r3);
#pragma unroll
            for (int off = 16; off > 0; off >>= 1)
                a += __shfl_xor_sync(0xffffffffu, a, off);
            if (lane == 0) {
                float x = a + b2;
                float* o = (p == 0) ? outp0 : outp1;
                o[k] = 1.0f / (1.0f + __expf(-x));
            }
        }
    }
}

__global__ void __launch_bounds__(256, 1)
score_kernel(const float* __restrict__ W2,
             const float* __restrict__ b2v,
             const int*   __restrict__ starts,
             const int*   __restrict__ maxd_p,
             float*       __restrict__ out)
{
    int i    = blockIdx.y;
    int j0   = blockIdx.x * 2;
    int j1   = j0 + 1;
    int lane = threadIdx.x & 31;
    int w    = threadIdx.x >> 5;

    int si   = starts[i];
    int maxd = maxd_p[0];
    float b2 = b2v[0];

    int dj0 = si - starts[j0]; if (dj0 < 0) dj0 = -dj0;
    int dj1 = si - starts[j1]; if (dj1 < 0) dj1 = -dj1;
    bool act0 = (i != j0) && (dj0 <= maxd);
    bool act1 = (i != j1) && (dj1 <= maxd);

    float* outp0 = out + ((size_t)i * E + j0) * R;
    float* outp1 = out + ((size_t)i * E + j1) * R;
    if (!act0 && threadIdx.x < R) outp0[threadIdx.x] = 0.f;
    if (!act1 && threadIdx.x < R) outp1[threadIdx.x] = 0.f;
    if (!act0 && !act1) return;

    const ulonglong2* P2  = (const ulonglong2*)(g_PQB + (size_t)i * H);
    const ulonglong2* W24 = (const ulonglong2*)W2;

    ull w01[8], w23[8];
    ull p01[8], p23[8];
#pragma unroll
    for (int q = 0; q < 8; q++) {
        ulonglong2 p  = P2 [lane + 32 * q];
        ulonglong2 ww = W24[lane + 32 * q];
        p01[q] = p.x;  p23[q] = p.y;
        w01[q] = ww.x; w23[q] = ww.y;
    }

    if (act0 && act1) {
        ull d01[2][8], d23[2][8];
        const ulonglong2* Q0 = (const ulonglong2*)(g_PQB + (size_t)(E + j0) * H);
        const ulonglong2* Q1 = (const ulonglong2*)(g_PQB + (size_t)(E + j1) * H);
#pragma unroll
        for (int q = 0; q < 8; q++) {
            ulonglong2 q0 = Q0[lane + 32 * q];
            ulonglong2 q1 = Q1[lane + 32 * q];
            d01[0][q] = f2add(p01[q], q0.x);
            d23[0][q] = f2add(p23[q], q0.y);
            d01[1][q] = f2add(p01[q], q1.x);
            d23[1][q] = f2add(p23[q], q1.y);
        }
        score_pairs<2>(d01, d23, w01, w23, lane, w, b2, outp0, outp1);
    } else {
        int ja = act0 ? j0 : j1;
        float* outpa = act0 ? outp0 : outp1;
        ull d01[1][8], d23[1][8];
        const ulonglong2* Qa = (const ulonglong2*)(g_PQB + (size_t)(E + ja) * H);
#pragma unroll
        for (int q = 0; q < 8; q++) {
            ulonglong2 qa = Qa[lane + 32 * q];
            d01[0][q] = f2add(p01[q], qa.x);
            d23[0][q] = f2add(p23[q], qa.y);
        }
        score_pairs<1>(d01, d23, w01, w23, lane, w, b2, outpa, outpa);
    }
}

// ---------------------------------------------------------------------------
// Inputs (metadata order):
//  0 entity_emb f32[48,1024]  1 rel_emb f32[32,1024]  2 W1 f32[3072,1024]
//  3 b1 f32[1024]  4 W2 f32[1024,1]  5 b2 f32[1]
//  6 entity_starts i32[48]    7 max_distance i32
// Output: f32 [48,48,32]
// ---------------------------------------------------------------------------
extern "C" void kernel_launch(void* const* d_in, const int* in_sizes, int n_in,
                              void* d_out, int out_size)
{
    const float* ent    = (const float*)d_in[0];
    const float* rel    = (const float*)d_in[1];
    const float* W1     = (const float*)d_in[2];
    const float* b1     = (const float*)d_in[3];
    const float* W2     = (const float*)d_in[4];
    const float* b2     = (const float*)d_in[5];
    const int*   starts = (const int*)  d_in[6];
    const int*   maxd   = (const int*)  d_in[7];
    float* out = (float*)d_out;

    precompute_kernel<<<dim3(64, 16), 128>>>(ent, rel, W1);
    reduce_kernel<<<128, 256>>>(b1);
    score_kernel<<<dim3(24, 48), 256>>>(W2, b2, starts, maxd, out);
}